// round 8
// baseline (speedup 1.0000x reference)
#include <cuda_runtime.h>

#define NN 100000
#define NE 1600000
#define DIM 128
#define DC 64
#define BN_EPS 1e-5f
#define CH ((NN + 1023) / 1024)   // 98 nodes per thread in the single-block scan

// ---------------- scratch (device globals; zero-initialized at load) -------
__device__ float g_buf_agg[NN * DIM];   // aggregated features / layer-3 g [N,64]
__device__ float g_buf_h[NN * DIM];     // hidden activations
__device__ float g_norm_src[NN];
__device__ float g_norm_dst[NN];
__device__ int   g_deg_out[NN];         // zeroed by tail k_reset each call
__device__ int   g_deg_in[NN];          // zeroed by tail k_reset each call
__device__ int   g_off[NN];             // CSR row offsets
__device__ int   g_cursor[NN];          // fill cursors (zeroed by tail k_reset)
__device__ int   g_csr_src[NE];         // CSR source index per in-edge
__device__ float g_sum0[DIM], g_sumsq0[DIM];   // layer-1 BN stats
__device__ float g_sum1[DIM], g_sumsq1[DIM];   // layer-2 BN stats
__device__ float g_mean[DIM], g_rstd[DIM];

#define BUF_AGG 0
#define BUF_H   1
__device__ __forceinline__ const float* buf_sel(int s) {
    return (s == BUF_AGG) ? g_buf_agg : g_buf_h;
}
__device__ __forceinline__ float* buf_sel_w(int s) {
    return (s == BUF_AGG) ? g_buf_agg : g_buf_h;
}

// ---------------- launch #1: degree count -----------------------------------
__global__ void k_count(const int* __restrict__ src, const int* __restrict__ dst) {
    int e = blockIdx.x * blockDim.x + threadIdx.x;
    if (e < NE) {
        atomicAdd(&g_deg_out[src[e]], 1);
        atomicAdd(&g_deg_in[dst[e]], 1);
    }
}

// ---------------- launch #2: scan + norms + stat-zero (single block) --------
__global__ void __launch_bounds__(1024) k_setup() {
    __shared__ int ssum[1024];
    int t = threadIdx.x;
    int base = t * CH;

    // serial chunk sum
    int local = 0;
    #pragma unroll 2
    for (int i = 0; i < CH; ++i) {
        int idx = base + i;
        if (idx < NN) local += g_deg_in[idx];
    }
    ssum[t] = local;
    __syncthreads();
    // inclusive block scan (Hillis-Steele)
    #pragma unroll
    for (int off = 1; off < 1024; off <<= 1) {
        int v = (t >= off) ? ssum[t - off] : 0;
        __syncthreads();
        ssum[t] += v;
        __syncthreads();
    }
    int run = ssum[t] - local;          // exclusive prefix of this chunk
    #pragma unroll 2
    for (int i = 0; i < CH; ++i) {
        int idx = base + i;
        if (idx < NN) {
            g_off[idx] = run;
            run += g_deg_in[idx];
        }
    }
    // norms (independent of scan result)
    for (int i = t; i < NN; i += 1024) {
        g_norm_src[i] = rsqrtf(fmaxf((float)g_deg_out[i], 1.0f));
        g_norm_dst[i] = rsqrtf(fmaxf((float)g_deg_in[i], 1.0f));
    }
    // zero BN stat accumulators for this call
    if (t < DIM) {
        g_sum0[t] = 0.f; g_sumsq0[t] = 0.f;
        g_sum1[t] = 0.f; g_sumsq1[t] = 0.f;
    }
}

// ---------------- launch #3: CSR fill ----------------------------------------
__global__ void k_fill_csr(const int* __restrict__ src, const int* __restrict__ dst) {
    int e = blockIdx.x * blockDim.x + threadIdx.x;
    if (e < NE) {
        int d = dst[e];
        int pos = atomicAdd(&g_cursor[d], 1);
        g_csr_src[g_off[d] + pos] = src[e];
    }
}

// ---------------- pull aggregation (128 wide) --------------------------------
// warp per dst node, 32 lanes x float4, 4-deep gather pipeline.
// BN folded: sum ns*(v-m)*rs = rs*(sum ns*v - m*sum ns).
template<int SRC_SEL, bool BN>
__global__ void __launch_bounds__(256) k_pull128(const float* __restrict__ hext) {
    int t = blockIdx.x * blockDim.x + threadIdx.x;
    int node = t >> 5;
    if (node >= NN) return;
    const float* __restrict__ h = (SRC_SEL < 0) ? hext : buf_sel(SRC_SEL);
    int lane = t & 31;
    int c = lane << 2;
    int start = g_off[node];
    int n = g_deg_in[node];

    float4 a0 = make_float4(0.f, 0.f, 0.f, 0.f);
    float4 a1 = make_float4(0.f, 0.f, 0.f, 0.f);
    float sns = 0.f;

    int j = 0;
    int end4 = n & ~3;
    for (; j < end4; j += 4) {
        int s0 = __ldg(&g_csr_src[start + j]);
        int s1 = __ldg(&g_csr_src[start + j + 1]);
        int s2 = __ldg(&g_csr_src[start + j + 2]);
        int s3 = __ldg(&g_csr_src[start + j + 3]);
        float n0 = __ldg(&g_norm_src[s0]);
        float n1 = __ldg(&g_norm_src[s1]);
        float n2 = __ldg(&g_norm_src[s2]);
        float n3 = __ldg(&g_norm_src[s3]);
        float4 v0 = *reinterpret_cast<const float4*>(h + (size_t)s0 * DIM + c);
        float4 v1 = *reinterpret_cast<const float4*>(h + (size_t)s1 * DIM + c);
        float4 v2 = *reinterpret_cast<const float4*>(h + (size_t)s2 * DIM + c);
        float4 v3 = *reinterpret_cast<const float4*>(h + (size_t)s3 * DIM + c);
        a0.x = fmaf(n0, v0.x, a0.x); a0.y = fmaf(n0, v0.y, a0.y);
        a0.z = fmaf(n0, v0.z, a0.z); a0.w = fmaf(n0, v0.w, a0.w);
        a1.x = fmaf(n1, v1.x, a1.x); a1.y = fmaf(n1, v1.y, a1.y);
        a1.z = fmaf(n1, v1.z, a1.z); a1.w = fmaf(n1, v1.w, a1.w);
        a0.x = fmaf(n2, v2.x, a0.x); a0.y = fmaf(n2, v2.y, a0.y);
        a0.z = fmaf(n2, v2.z, a0.z); a0.w = fmaf(n2, v2.w, a0.w);
        a1.x = fmaf(n3, v3.x, a1.x); a1.y = fmaf(n3, v3.y, a1.y);
        a1.z = fmaf(n3, v3.z, a1.z); a1.w = fmaf(n3, v3.w, a1.w);
        if (BN) sns += (n0 + n1) + (n2 + n3);
    }
    for (; j < n; ++j) {
        int s0 = __ldg(&g_csr_src[start + j]);
        float n0 = __ldg(&g_norm_src[s0]);
        float4 v0 = *reinterpret_cast<const float4*>(h + (size_t)s0 * DIM + c);
        a0.x = fmaf(n0, v0.x, a0.x); a0.y = fmaf(n0, v0.y, a0.y);
        a0.z = fmaf(n0, v0.z, a0.z); a0.w = fmaf(n0, v0.w, a0.w);
        if (BN) sns += n0;
    }
    a0.x += a1.x; a0.y += a1.y; a0.z += a1.z; a0.w += a1.w;

    if (BN) {
        float4 m  = *reinterpret_cast<const float4*>(g_mean + c);
        float4 rs = *reinterpret_cast<const float4*>(g_rstd + c);
        a0.x = (a0.x - m.x * sns) * rs.x;
        a0.y = (a0.y - m.y * sns) * rs.y;
        a0.z = (a0.z - m.z * sns) * rs.z;
        a0.w = (a0.w - m.w * sns) * rs.w;
    }
    float nd = g_norm_dst[node];
    a0.x *= nd; a0.y *= nd; a0.z *= nd; a0.w *= nd;
    *reinterpret_cast<float4*>(g_buf_agg + (size_t)node * DIM + c) = a0;
}

// ---------------- pull aggregation (64 wide, final layer) --------------------
// half-warp per dst node; out = acc * norm_dst + b2. norm_src already in g.
__global__ void __launch_bounds__(256) k_pull64(float* __restrict__ out,
                                                const float* __restrict__ b2) {
    int t = blockIdx.x * blockDim.x + threadIdx.x;
    int node = t >> 4;
    if (node >= NN) return;
    const float* __restrict__ g = g_buf_agg;
    int lane = t & 15;
    int c = lane << 2;
    int start = g_off[node];
    int n = g_deg_in[node];

    float4 a0 = make_float4(0.f, 0.f, 0.f, 0.f);
    float4 a1 = make_float4(0.f, 0.f, 0.f, 0.f);

    int j = 0;
    int end4 = n & ~3;
    for (; j < end4; j += 4) {
        int s0 = __ldg(&g_csr_src[start + j]);
        int s1 = __ldg(&g_csr_src[start + j + 1]);
        int s2 = __ldg(&g_csr_src[start + j + 2]);
        int s3 = __ldg(&g_csr_src[start + j + 3]);
        float4 v0 = *reinterpret_cast<const float4*>(g + (size_t)s0 * DC + c);
        float4 v1 = *reinterpret_cast<const float4*>(g + (size_t)s1 * DC + c);
        float4 v2 = *reinterpret_cast<const float4*>(g + (size_t)s2 * DC + c);
        float4 v3 = *reinterpret_cast<const float4*>(g + (size_t)s3 * DC + c);
        a0.x += v0.x + v2.x; a0.y += v0.y + v2.y;
        a0.z += v0.z + v2.z; a0.w += v0.w + v2.w;
        a1.x += v1.x + v3.x; a1.y += v1.y + v3.y;
        a1.z += v1.z + v3.z; a1.w += v1.w + v3.w;
    }
    for (; j < n; ++j) {
        int s0 = __ldg(&g_csr_src[start + j]);
        float4 v0 = *reinterpret_cast<const float4*>(g + (size_t)s0 * DC + c);
        a0.x += v0.x; a0.y += v0.y; a0.z += v0.z; a0.w += v0.w;
    }
    a0.x += a1.x; a0.y += a1.y; a0.z += a1.z; a0.w += a1.w;

    float nd = g_norm_dst[node];
    float4 b = *reinterpret_cast<const float4*>(b2 + c);
    a0.x = fmaf(a0.x, nd, b.x);
    a0.y = fmaf(a0.y, nd, b.y);
    a0.z = fmaf(a0.z, nd, b.z);
    a0.w = fmaf(a0.w, nd, b.w);
    *reinterpret_cast<float4*>(out + (size_t)node * DC + c) = a0;
}

// ---------------- fused GEMM (+ optional BN-stats epilogue) ------------------
// out[r,:] = act( (xf(IN[r,:]) * scale) @ W + bias ),  K = 128 fixed.
// SCALE_MODE: 0 = none, 1 = norm_src. STATS: -1 none, 0 -> sum0, 1 -> sum1.
template<int OUTW, int IN_SEL, int OUT_SEL, bool BN_IN, bool BIAS_RELU, int SCALE_MODE, int STATS>
__global__ void __launch_bounds__(256) k_gemm(const float* __restrict__ W,
                                              const float* __restrict__ bias) {
    constexpr int CT = OUTW / 16;       // cols per thread (8 or 4)
    __shared__ float As[64 * 132];      // 33 KB; also reused for stats reduce

    const float* __restrict__ A = buf_sel(IN_SEL);
    float* __restrict__ out = buf_sel_w(OUT_SEL);

    int rowBase = blockIdx.x * 64;

    #pragma unroll
    for (int it = 0; it < 8; ++it) {
        int idx = threadIdx.x + it * 256;
        int r   = idx >> 5;
        int c   = (idx & 31) << 2;
        int row = rowBase + r;
        float4 v = make_float4(0.f, 0.f, 0.f, 0.f);
        if (row < NN) {
            v = *reinterpret_cast<const float4*>(A + (size_t)row * DIM + c);
            if (BN_IN) {
                float4 m  = *reinterpret_cast<const float4*>(g_mean + c);
                float4 rs = *reinterpret_cast<const float4*>(g_rstd + c);
                v.x = (v.x - m.x) * rs.x;
                v.y = (v.y - m.y) * rs.y;
                v.z = (v.z - m.z) * rs.z;
                v.w = (v.w - m.w) * rs.w;
            }
            if (SCALE_MODE == 1) {
                float sc = g_norm_src[row];
                v.x *= sc; v.y *= sc; v.z *= sc; v.w *= sc;
            }
        }
        *reinterpret_cast<float4*>(&As[r * 132 + c]) = v;
    }
    __syncthreads();

    int tr = threadIdx.x >> 4;          // 0..15 (row group)
    int tc = threadIdx.x & 15;          // 0..15 (col group)
    const float* A0 = &As[(tr * 4) * 132];

    float acc[4][CT];
    #pragma unroll
    for (int i = 0; i < 4; ++i)
        #pragma unroll
        for (int j = 0; j < CT; ++j) acc[i][j] = 0.f;

    #pragma unroll 4
    for (int k = 0; k < 128; ++k) {
        float a0 = A0[k];
        float a1 = A0[132 + k];
        float a2 = A0[264 + k];
        float a3 = A0[396 + k];
        const float* wrow = W + k * OUTW + tc * CT;
        float4 w0 = __ldg(reinterpret_cast<const float4*>(wrow));
        float wv[CT];
        wv[0] = w0.x; wv[1] = w0.y; wv[2] = w0.z; wv[3] = w0.w;
        if (CT == 8) {
            float4 w1 = __ldg(reinterpret_cast<const float4*>(wrow + 4));
            wv[4] = w1.x; wv[5] = w1.y; wv[6] = w1.z; wv[7] = w1.w;
        }
        #pragma unroll
        for (int j = 0; j < CT; ++j) {
            acc[0][j] = fmaf(a0, wv[j], acc[0][j]);
            acc[1][j] = fmaf(a1, wv[j], acc[1][j]);
            acc[2][j] = fmaf(a2, wv[j], acc[2][j]);
            acc[3][j] = fmaf(a3, wv[j], acc[3][j]);
        }
    }

    // epilogue: bias + relu in registers, store, optional stats
    float bv[CT];
    if (BIAS_RELU) {
        #pragma unroll
        for (int j0 = 0; j0 < CT; j0 += 4) {
            float4 b = __ldg(reinterpret_cast<const float4*>(bias + tc * CT + j0));
            bv[j0] = b.x; bv[j0 + 1] = b.y; bv[j0 + 2] = b.z; bv[j0 + 3] = b.w;
        }
    }
    #pragma unroll
    for (int i = 0; i < 4; ++i) {
        int row = rowBase + tr * 4 + i;
        bool valid = row < NN;
        #pragma unroll
        for (int j = 0; j < CT; ++j) {
            float y = acc[i][j];
            if (BIAS_RELU) y = fmaxf(y + bv[j], 0.f);
            acc[i][j] = valid ? y : 0.f;
        }
        if (valid) {
            #pragma unroll
            for (int j0 = 0; j0 < CT; j0 += 4) {
                float4 y4;
                y4.x = acc[i][j0 + 0]; y4.y = acc[i][j0 + 1];
                y4.z = acc[i][j0 + 2]; y4.w = acc[i][j0 + 3];
                *reinterpret_cast<float4*>(out + (size_t)row * OUTW + tc * CT + j0) = y4;
            }
        }
    }

    if (STATS >= 0) {
        float* SUM = (STATS == 0) ? g_sum0 : g_sum1;
        float* SQ  = (STATS == 0) ? g_sumsq0 : g_sumsq1;
        float* sh = As;                  // reuse: [0..2047] sums, [2048..4095] sqs
        __syncthreads();                 // all As reads from main loop complete
        #pragma unroll
        for (int j = 0; j < CT; ++j) {
            float s = (acc[0][j] + acc[1][j]) + (acc[2][j] + acc[3][j]);
            float q = fmaf(acc[0][j], acc[0][j],
                      fmaf(acc[1][j], acc[1][j],
                      fmaf(acc[2][j], acc[2][j], acc[3][j] * acc[3][j])));
            int col = tc * CT + j;
            sh[tr * 128 + col] = s;
            sh[2048 + tr * 128 + col] = q;
        }
        __syncthreads();
        if (threadIdx.x < 128) {
            int col = threadIdx.x;
            float s = 0.f, q = 0.f;
            #pragma unroll
            for (int k2 = 0; k2 < 16; ++k2) {
                s += sh[k2 * 128 + col];
                q += sh[2048 + k2 * 128 + col];
            }
            atomicAdd(&SUM[col], s);
            atomicAdd(&SQ[col], q);
        }
    }
}

// ---------------- finalize BN stats ------------------------------------------
template<int L>
__global__ void k_finalize_stats() {
    int i = threadIdx.x;
    if (i < DIM) {
        const float* S = (L == 0) ? g_sum0 : g_sum1;
        const float* Q = (L == 0) ? g_sumsq0 : g_sumsq1;
        float inv = 1.0f / (float)NN;
        float mean = S[i] * inv;
        float var  = fmaxf(Q[i] * inv - mean * mean, 0.f);
        g_mean[i] = mean;
        g_rstd[i] = rsqrtf(var + BN_EPS);
    }
}

// ---------------- tail reset: leave counters zeroed for next call ------------
__global__ void k_reset() {
    int i = blockIdx.x * blockDim.x + threadIdx.x;
    if (i < NN) { g_deg_out[i] = 0; g_deg_in[i] = 0; g_cursor[i] = 0; }
}

// ---------------- launch ----------------------------------------------------
extern "C" void kernel_launch(void* const* d_in, const int* in_sizes, int n_in,
                              void* d_out, int out_size) {
    const float* features = (const float*)d_in[0];
    const float* W0 = (const float*)d_in[1];
    const float* b0 = (const float*)d_in[2];
    const float* W1 = (const float*)d_in[3];
    const float* b1 = (const float*)d_in[4];
    const float* W2 = (const float*)d_in[5];
    const float* b2 = (const float*)d_in[6];
    const int* src = (const int*)d_in[7];
    const int* dst = (const int*)d_in[8];
    float* out = (float*)d_out;

    const int TB = 256;
    const int gN      = (NN + TB - 1) / TB;
    const int gE      = (NE + TB - 1) / TB;
    const int gPull   = (NN * 32 + TB - 1) / TB;   // warp per node
    const int gPull64 = (NN * 16 + TB - 1) / TB;   // half-warp per node
    const int gGemm   = (NN + 63) / 64;

    // setup (counters arrive zeroed: zero-init on first call, k_reset after)
    k_count<<<gE, TB>>>(src, dst);                                   // #1
    k_setup<<<1, 1024>>>();                                          // #2
    k_fill_csr<<<gE, TB>>>(src, dst);                                // #3

    // layer 1
    k_pull128<-1, false><<<gPull, TB>>>(features);                   // #4 (profiled)
    k_gemm<128, BUF_AGG, BUF_H, false, true, 0, 0><<<gGemm, TB>>>(W0, b0);
    k_finalize_stats<0><<<1, 128>>>();

    // layer 2 (BN folded into pull)
    k_pull128<BUF_H, true><<<gPull, TB>>>(nullptr);
    k_gemm<128, BUF_AGG, BUF_H, false, true, 0, 1><<<gGemm, TB>>>(W1, b1);
    k_finalize_stats<1><<<1, 128>>>();

    // layer 3: GEMM first (128->64), then pull with nd+bias epilogue
    k_gemm<64, BUF_H, BUF_AGG, true, false, 1, -1><<<gGemm, TB>>>(W2, nullptr);
    k_pull64<<<gPull64, TB>>>(out, b2);

    // leave counters zeroed for the next invocation
    k_reset<<<gN, TB>>>();
}

// round 9
// speedup vs baseline: 1.2174x; 1.2174x over previous
#include <cuda_runtime.h>

#define NN 100000
#define NE 1600000
#define DIM 128
#define DC 64
#define BN_EPS 1e-5f
#define SCAN_B 1024
#define NB ((NN + SCAN_B - 1) / SCAN_B)   // 98

// ---------------- scratch (device globals; zero-initialized at load) -------
__device__ float g_buf_agg[NN * DIM];   // aggregated features / layer-3 g [N,64]
__device__ float g_buf_h[NN * DIM];     // hidden activations (pre-scaled by ns)
__device__ float g_norm_src[NN];
__device__ float g_norm_dst[NN];
__device__ float g_sns[NN];             // sum of norm_src over in-neighbors (reset tail)
__device__ int   g_deg_out[NN];         // reset tail
__device__ int   g_deg_in[NN];          // reset tail
__device__ int   g_off[NN];             // CSR offsets, exclusive WITHIN scan block
__device__ int   g_blockoff[NB];        // per-scanblock global offset
__device__ int   g_blocksum[NB];
__device__ int   g_cursor[NN];          // fill cursors (reset tail)
__device__ int   g_csr_src[NE];
__device__ float g_sum0[DIM], g_sumsq0[DIM];
__device__ float g_sum1[DIM], g_sumsq1[DIM];
__device__ float g_mean[DIM], g_rstd[DIM];

#define BUF_AGG 0
#define BUF_H   1
__device__ __forceinline__ const float* buf_sel(int s) {
    return (s == BUF_AGG) ? g_buf_agg : g_buf_h;
}
__device__ __forceinline__ float* buf_sel_w(int s) {
    return (s == BUF_AGG) ? g_buf_agg : g_buf_h;
}

__device__ __forceinline__ int csr_start(int node) {
    return g_off[node] + g_blockoff[node >> 10];
}

// ---------------- setup -------------------------------------------------------
__global__ void k_count(const int* __restrict__ src, const int* __restrict__ dst) {
    int e = blockIdx.x * blockDim.x + threadIdx.x;
    if (e < NE) {
        atomicAdd(&g_deg_out[src[e]], 1);
        atomicAdd(&g_deg_in[dst[e]], 1);
    }
}

__global__ void __launch_bounds__(SCAN_B) k_scan_local() {
    __shared__ int s[SCAN_B];
    int i = blockIdx.x * SCAN_B + threadIdx.x;
    int x = (i < NN) ? g_deg_in[i] : 0;
    s[threadIdx.x] = x;
    __syncthreads();
    #pragma unroll
    for (int off = 1; off < SCAN_B; off <<= 1) {
        int v = (threadIdx.x >= off) ? s[threadIdx.x - off] : 0;
        __syncthreads();
        s[threadIdx.x] += v;
        __syncthreads();
    }
    if (i < NN) g_off[i] = s[threadIdx.x] - x;   // exclusive within block
    if (threadIdx.x == SCAN_B - 1) g_blocksum[blockIdx.x] = s[SCAN_B - 1];
}

__global__ void k_scan_block() {
    __shared__ int s[NB];
    if (threadIdx.x < NB) s[threadIdx.x] = g_blocksum[threadIdx.x];
    __syncthreads();
    if (threadIdx.x == 0) {
        int acc = 0;
        for (int b = 0; b < NB; ++b) { int v = s[b]; s[b] = acc; acc += v; }
    }
    __syncthreads();
    if (threadIdx.x < NB) g_blockoff[threadIdx.x] = s[threadIdx.x];
}

// norms + zero BN stat accumulators
__global__ void k_norms() {
    int i = blockIdx.x * blockDim.x + threadIdx.x;
    if (i < NN) {
        g_norm_src[i] = rsqrtf(fmaxf((float)g_deg_out[i], 1.0f));
        g_norm_dst[i] = rsqrtf(fmaxf((float)g_deg_in[i], 1.0f));
    }
    if (blockIdx.x == 0 && threadIdx.x < DIM) {
        g_sum0[threadIdx.x] = 0.f; g_sumsq0[threadIdx.x] = 0.f;
        g_sum1[threadIdx.x] = 0.f; g_sumsq1[threadIdx.x] = 0.f;
    }
}

// CSR fill + accumulate sns[d] = sum of norm_src over in-neighbors
__global__ void k_fill_csr(const int* __restrict__ src, const int* __restrict__ dst) {
    int e = blockIdx.x * blockDim.x + threadIdx.x;
    if (e < NE) {
        int d = dst[e];
        int s = src[e];
        int pos = atomicAdd(&g_cursor[d], 1);
        g_csr_src[g_off[d] + g_blockoff[d >> 10] + pos] = s;
        atomicAdd(&g_sns[d], g_norm_src[s]);
    }
}

// ---------------- pull, layer 1 (gathers raw features, needs per-edge norm) --
__global__ void __launch_bounds__(256) k_pull128_l1(const float* __restrict__ h) {
    int t = blockIdx.x * blockDim.x + threadIdx.x;
    int node = t >> 5;
    if (node >= NN) return;
    int lane = t & 31;
    int c = lane << 2;
    int start = csr_start(node);
    int n = g_deg_in[node];

    float4 a0 = make_float4(0.f, 0.f, 0.f, 0.f);
    float4 a1 = make_float4(0.f, 0.f, 0.f, 0.f);

    int j = 0;
    int end4 = n & ~3;
    for (; j < end4; j += 4) {
        int s0 = __ldg(&g_csr_src[start + j]);
        int s1 = __ldg(&g_csr_src[start + j + 1]);
        int s2 = __ldg(&g_csr_src[start + j + 2]);
        int s3 = __ldg(&g_csr_src[start + j + 3]);
        float n0 = __ldg(&g_norm_src[s0]);
        float n1 = __ldg(&g_norm_src[s1]);
        float n2 = __ldg(&g_norm_src[s2]);
        float n3 = __ldg(&g_norm_src[s3]);
        float4 v0 = *reinterpret_cast<const float4*>(h + (size_t)s0 * DIM + c);
        float4 v1 = *reinterpret_cast<const float4*>(h + (size_t)s1 * DIM + c);
        float4 v2 = *reinterpret_cast<const float4*>(h + (size_t)s2 * DIM + c);
        float4 v3 = *reinterpret_cast<const float4*>(h + (size_t)s3 * DIM + c);
        a0.x = fmaf(n0, v0.x, a0.x); a0.y = fmaf(n0, v0.y, a0.y);
        a0.z = fmaf(n0, v0.z, a0.z); a0.w = fmaf(n0, v0.w, a0.w);
        a1.x = fmaf(n1, v1.x, a1.x); a1.y = fmaf(n1, v1.y, a1.y);
        a1.z = fmaf(n1, v1.z, a1.z); a1.w = fmaf(n1, v1.w, a1.w);
        a0.x = fmaf(n2, v2.x, a0.x); a0.y = fmaf(n2, v2.y, a0.y);
        a0.z = fmaf(n2, v2.z, a0.z); a0.w = fmaf(n2, v2.w, a0.w);
        a1.x = fmaf(n3, v3.x, a1.x); a1.y = fmaf(n3, v3.y, a1.y);
        a1.z = fmaf(n3, v3.z, a1.z); a1.w = fmaf(n3, v3.w, a1.w);
    }
    for (; j < n; ++j) {
        int s0 = __ldg(&g_csr_src[start + j]);
        float n0 = __ldg(&g_norm_src[s0]);
        float4 v0 = *reinterpret_cast<const float4*>(h + (size_t)s0 * DIM + c);
        a0.x = fmaf(n0, v0.x, a0.x); a0.y = fmaf(n0, v0.y, a0.y);
        a0.z = fmaf(n0, v0.z, a0.z); a0.w = fmaf(n0, v0.w, a0.w);
    }
    a0.x += a1.x; a0.y += a1.y; a0.z += a1.z; a0.w += a1.w;

    float nd = g_norm_dst[node];
    a0.x *= nd; a0.y *= nd; a0.z *= nd; a0.w *= nd;
    *reinterpret_cast<float4*>(g_buf_agg + (size_t)node * DIM + c) = a0;
}

// ---------------- pull, layer 2 (pure row-sum; h pre-scaled by ns) -----------
// agg = nd * rs * (sum h'_s  -  mean * sns[node])
__global__ void __launch_bounds__(256) k_pull128_fast() {
    int t = blockIdx.x * blockDim.x + threadIdx.x;
    int node = t >> 5;
    if (node >= NN) return;
    const float* __restrict__ h = g_buf_h;
    int lane = t & 31;
    int c = lane << 2;
    int start = csr_start(node);
    int n = g_deg_in[node];

    float4 a0 = make_float4(0.f, 0.f, 0.f, 0.f);
    float4 a1 = make_float4(0.f, 0.f, 0.f, 0.f);

    int j = 0;
    int end4 = n & ~3;
    for (; j < end4; j += 4) {
        int s0 = __ldg(&g_csr_src[start + j]);
        int s1 = __ldg(&g_csr_src[start + j + 1]);
        int s2 = __ldg(&g_csr_src[start + j + 2]);
        int s3 = __ldg(&g_csr_src[start + j + 3]);
        float4 v0 = *reinterpret_cast<const float4*>(h + (size_t)s0 * DIM + c);
        float4 v1 = *reinterpret_cast<const float4*>(h + (size_t)s1 * DIM + c);
        float4 v2 = *reinterpret_cast<const float4*>(h + (size_t)s2 * DIM + c);
        float4 v3 = *reinterpret_cast<const float4*>(h + (size_t)s3 * DIM + c);
        a0.x += v0.x + v2.x; a0.y += v0.y + v2.y;
        a0.z += v0.z + v2.z; a0.w += v0.w + v2.w;
        a1.x += v1.x + v3.x; a1.y += v1.y + v3.y;
        a1.z += v1.z + v3.z; a1.w += v1.w + v3.w;
    }
    for (; j < n; ++j) {
        int s0 = __ldg(&g_csr_src[start + j]);
        float4 v0 = *reinterpret_cast<const float4*>(h + (size_t)s0 * DIM + c);
        a0.x += v0.x; a0.y += v0.y; a0.z += v0.z; a0.w += v0.w;
    }
    a0.x += a1.x; a0.y += a1.y; a0.z += a1.z; a0.w += a1.w;

    float sns = g_sns[node];
    float nd  = g_norm_dst[node];
    float4 m  = *reinterpret_cast<const float4*>(g_mean + c);
    float4 rs = *reinterpret_cast<const float4*>(g_rstd + c);
    a0.x = (a0.x - m.x * sns) * rs.x * nd;
    a0.y = (a0.y - m.y * sns) * rs.y * nd;
    a0.z = (a0.z - m.z * sns) * rs.z * nd;
    a0.w = (a0.w - m.w * sns) * rs.w * nd;
    *reinterpret_cast<float4*>(g_buf_agg + (size_t)node * DIM + c) = a0;
}

// ---------------- pull, final layer (64 wide) ---------------------------------
__global__ void __launch_bounds__(256) k_pull64(float* __restrict__ out,
                                                const float* __restrict__ b2) {
    int t = blockIdx.x * blockDim.x + threadIdx.x;
    int node = t >> 4;
    if (node >= NN) return;
    const float* __restrict__ g = g_buf_agg;
    int lane = t & 15;
    int c = lane << 2;
    int start = csr_start(node);
    int n = g_deg_in[node];

    float4 a0 = make_float4(0.f, 0.f, 0.f, 0.f);
    float4 a1 = make_float4(0.f, 0.f, 0.f, 0.f);

    int j = 0;
    int end4 = n & ~3;
    for (; j < end4; j += 4) {
        int s0 = __ldg(&g_csr_src[start + j]);
        int s1 = __ldg(&g_csr_src[start + j + 1]);
        int s2 = __ldg(&g_csr_src[start + j + 2]);
        int s3 = __ldg(&g_csr_src[start + j + 3]);
        float4 v0 = *reinterpret_cast<const float4*>(g + (size_t)s0 * DC + c);
        float4 v1 = *reinterpret_cast<const float4*>(g + (size_t)s1 * DC + c);
        float4 v2 = *reinterpret_cast<const float4*>(g + (size_t)s2 * DC + c);
        float4 v3 = *reinterpret_cast<const float4*>(g + (size_t)s3 * DC + c);
        a0.x += v0.x + v2.x; a0.y += v0.y + v2.y;
        a0.z += v0.z + v2.z; a0.w += v0.w + v2.w;
        a1.x += v1.x + v3.x; a1.y += v1.y + v3.y;
        a1.z += v1.z + v3.z; a1.w += v1.w + v3.w;
    }
    for (; j < n; ++j) {
        int s0 = __ldg(&g_csr_src[start + j]);
        float4 v0 = *reinterpret_cast<const float4*>(g + (size_t)s0 * DC + c);
        a0.x += v0.x; a0.y += v0.y; a0.z += v0.z; a0.w += v0.w;
    }
    a0.x += a1.x; a0.y += a1.y; a0.z += a1.z; a0.w += a1.w;

    float nd = g_norm_dst[node];
    float4 b = *reinterpret_cast<const float4*>(b2 + c);
    a0.x = fmaf(a0.x, nd, b.x);
    a0.y = fmaf(a0.y, nd, b.y);
    a0.z = fmaf(a0.z, nd, b.z);
    a0.w = fmaf(a0.w, nd, b.w);
    *reinterpret_cast<float4*>(out + (size_t)node * DC + c) = a0;
}

// ---------------- fused GEMM --------------------------------------------------
// XFORM: 0 none; 1 = (v - mean*ns[row]) * rstd   (layer-3 input, h pre-scaled)
// OUT_SCALE: multiply stored output by ns[row] (stats computed pre-scale)
// STATS: -1 none, 0 -> sum0, 1 -> sum1
template<int OUTW, int IN_SEL, int OUT_SEL, int XFORM, bool BIAS_RELU, bool OUT_SCALE, int STATS>
__global__ void __launch_bounds__(256) k_gemm(const float* __restrict__ W,
                                              const float* __restrict__ bias) {
    constexpr int CT = OUTW / 16;
    __shared__ float As[64 * 132];

    const float* __restrict__ A = buf_sel(IN_SEL);
    float* __restrict__ out = buf_sel_w(OUT_SEL);

    int rowBase = blockIdx.x * 64;

    #pragma unroll
    for (int it = 0; it < 8; ++it) {
        int idx = threadIdx.x + it * 256;
        int r   = idx >> 5;
        int c   = (idx & 31) << 2;
        int row = rowBase + r;
        float4 v = make_float4(0.f, 0.f, 0.f, 0.f);
        if (row < NN) {
            v = *reinterpret_cast<const float4*>(A + (size_t)row * DIM + c);
            if (XFORM == 1) {
                float ns = g_norm_src[row];
                float4 m  = *reinterpret_cast<const float4*>(g_mean + c);
                float4 rs = *reinterpret_cast<const float4*>(g_rstd + c);
                v.x = (v.x - m.x * ns) * rs.x;
                v.y = (v.y - m.y * ns) * rs.y;
                v.z = (v.z - m.z * ns) * rs.z;
                v.w = (v.w - m.w * ns) * rs.w;
            }
        }
        *reinterpret_cast<float4*>(&As[r * 132 + c]) = v;
    }
    __syncthreads();

    int tr = threadIdx.x >> 4;
    int tc = threadIdx.x & 15;
    const float* A0 = &As[(tr * 4) * 132];

    float acc[4][CT];
    #pragma unroll
    for (int i = 0; i < 4; ++i)
        #pragma unroll
        for (int j = 0; j < CT; ++j) acc[i][j] = 0.f;

    #pragma unroll 4
    for (int k = 0; k < 128; ++k) {
        float a0 = A0[k];
        float a1 = A0[132 + k];
        float a2 = A0[264 + k];
        float a3 = A0[396 + k];
        const float* wrow = W + k * OUTW + tc * CT;
        float4 w0 = __ldg(reinterpret_cast<const float4*>(wrow));
        float wv[CT];
        wv[0] = w0.x; wv[1] = w0.y; wv[2] = w0.z; wv[3] = w0.w;
        if (CT == 8) {
            float4 w1 = __ldg(reinterpret_cast<const float4*>(wrow + 4));
            wv[4] = w1.x; wv[5] = w1.y; wv[6] = w1.z; wv[7] = w1.w;
        }
        #pragma unroll
        for (int j = 0; j < CT; ++j) {
            acc[0][j] = fmaf(a0, wv[j], acc[0][j]);
            acc[1][j] = fmaf(a1, wv[j], acc[1][j]);
            acc[2][j] = fmaf(a2, wv[j], acc[2][j]);
            acc[3][j] = fmaf(a3, wv[j], acc[3][j]);
        }
    }

    float bv[CT];
    if (BIAS_RELU) {
        #pragma unroll
        for (int j0 = 0; j0 < CT; j0 += 4) {
            float4 b = __ldg(reinterpret_cast<const float4*>(bias + tc * CT + j0));
            bv[j0] = b.x; bv[j0 + 1] = b.y; bv[j0 + 2] = b.z; bv[j0 + 3] = b.w;
        }
    }
    #pragma unroll
    for (int i = 0; i < 4; ++i) {
        int row = rowBase + tr * 4 + i;
        bool valid = row < NN;
        #pragma unroll
        for (int j = 0; j < CT; ++j) {
            float y = acc[i][j];
            if (BIAS_RELU) y = fmaxf(y + bv[j], 0.f);
            acc[i][j] = valid ? y : 0.f;       // acc holds h (pre-scale) for stats
        }
        if (valid) {
            float osc = OUT_SCALE ? __ldg(&g_norm_src[row]) : 1.0f;
            #pragma unroll
            for (int j0 = 0; j0 < CT; j0 += 4) {
                float4 y4;
                y4.x = acc[i][j0 + 0] * osc; y4.y = acc[i][j0 + 1] * osc;
                y4.z = acc[i][j0 + 2] * osc; y4.w = acc[i][j0 + 3] * osc;
                *reinterpret_cast<float4*>(out + (size_t)row * OUTW + tc * CT + j0) = y4;
            }
        }
    }

    if (STATS >= 0) {
        float* SUM = (STATS == 0) ? g_sum0 : g_sum1;
        float* SQ  = (STATS == 0) ? g_sumsq0 : g_sumsq1;
        float* sh = As;
        __syncthreads();
        #pragma unroll
        for (int j = 0; j < CT; ++j) {
            float s = (acc[0][j] + acc[1][j]) + (acc[2][j] + acc[3][j]);
            float q = fmaf(acc[0][j], acc[0][j],
                      fmaf(acc[1][j], acc[1][j],
                      fmaf(acc[2][j], acc[2][j], acc[3][j] * acc[3][j])));
            int col = tc * CT + j;
            sh[tr * 128 + col] = s;
            sh[2048 + tr * 128 + col] = q;
        }
        __syncthreads();
        if (threadIdx.x < 128) {
            int col = threadIdx.x;
            float s = 0.f, q = 0.f;
            #pragma unroll
            for (int k2 = 0; k2 < 16; ++k2) {
                s += sh[k2 * 128 + col];
                q += sh[2048 + k2 * 128 + col];
            }
            atomicAdd(&SUM[col], s);
            atomicAdd(&SQ[col], q);
        }
    }
}

// ---------------- finalize BN stats -------------------------------------------
template<int L>
__global__ void k_finalize_stats() {
    int i = threadIdx.x;
    if (i < DIM) {
        const float* S = (L == 0) ? g_sum0 : g_sum1;
        const float* Q = (L == 0) ? g_sumsq0 : g_sumsq1;
        float inv = 1.0f / (float)NN;
        float mean = S[i] * inv;
        float var  = fmaxf(Q[i] * inv - mean * mean, 0.f);
        g_mean[i] = mean;
        g_rstd[i] = rsqrtf(var + BN_EPS);
    }
}

// ---------------- tail reset ----------------------------------------------------
__global__ void k_reset() {
    int i = blockIdx.x * blockDim.x + threadIdx.x;
    if (i < NN) {
        g_deg_out[i] = 0; g_deg_in[i] = 0;
        g_cursor[i] = 0;  g_sns[i] = 0.f;
    }
}

// ---------------- launch ---------------------------------------------------------
extern "C" void kernel_launch(void* const* d_in, const int* in_sizes, int n_in,
                              void* d_out, int out_size) {
    const float* features = (const float*)d_in[0];
    const float* W0 = (const float*)d_in[1];
    const float* b0 = (const float*)d_in[2];
    const float* W1 = (const float*)d_in[3];
    const float* b1 = (const float*)d_in[4];
    const float* W2 = (const float*)d_in[5];
    const float* b2 = (const float*)d_in[6];
    const int* src = (const int*)d_in[7];
    const int* dst = (const int*)d_in[8];
    float* out = (float*)d_out;

    const int TB = 256;
    const int gN      = (NN + TB - 1) / TB;
    const int gE      = (NE + TB - 1) / TB;
    const int gPull   = (NN * 32 + TB - 1) / TB;
    const int gPull64 = (NN * 16 + TB - 1) / TB;
    const int gGemm   = (NN + 63) / 64;

    // setup (counters arrive zeroed: zero-init first call, k_reset tail after)
    k_count<<<gE, TB>>>(src, dst);          // #1
    k_scan_local<<<NB, SCAN_B>>>();         // #2
    k_scan_block<<<1, 128>>>();             // #3
    k_norms<<<gN, TB>>>();                  // #4
    k_fill_csr<<<gE, TB>>>(src, dst);       // #5

    // layer 1: agg = nd * A~(ns*feat); h' = ns * relu(agg @ W0 + b0); stats on h
    k_pull128_l1<<<gPull, TB>>>(features);
    k_gemm<128, BUF_AGG, BUF_H, 0, true, true, 0><<<gGemm, TB>>>(W0, b0);
    k_finalize_stats<0><<<1, 128>>>();

    // layer 2: pure-sum pull with BN-fold epilogue; h' = ns * relu(...)
    k_pull128_fast<<<gPull, TB>>>();
    k_gemm<128, BUF_AGG, BUF_H, 0, true, true, 1><<<gGemm, TB>>>(W1, b1);
    k_finalize_stats<1><<<1, 128>>>();

    // layer 3: g = ((h' - m*ns)*rs) @ W2, then pure-sum pull + nd,b2 epilogue
    k_gemm<64, BUF_H, BUF_AGG, 1, false, false, -1><<<gGemm, TB>>>(W2, nullptr);
    k_pull64<<<gPull64, TB>>>(out, b2);

    // leave counters zeroed for next invocation
    k_reset<<<gN, TB>>>();
}

// round 10
// speedup vs baseline: 1.2659x; 1.0399x over previous
#include <cuda_runtime.h>

#define NN 100000
#define NE 1600000
#define DIM 128
#define DC 64
#define BN_EPS 1e-5f
#define SCAN_B 1024
#define NB ((NN + SCAN_B - 1) / SCAN_B)   // 98

// ---------------- f32x2 packed-math helpers (Blackwell full-rate fp32) ------
typedef unsigned long long u64;

__device__ __forceinline__ u64 pack2(float lo, float hi) {
    u64 r;
    asm("mov.b64 %0, {%1, %2};" : "=l"(r) : "f"(lo), "f"(hi));
    return r;
}
__device__ __forceinline__ u64 pack_dup(float v) {
    u64 r;
    asm("mov.b64 %0, {%1, %1};" : "=l"(r) : "f"(v));
    return r;
}
__device__ __forceinline__ void unpack2(u64 v, float& lo, float& hi) {
    asm("mov.b64 {%0, %1}, %2;" : "=f"(lo), "=f"(hi) : "l"(v));
}
#define FMA2(acc, a, b) \
    asm("fma.rn.f32x2 %0, %1, %2, %0;" : "+l"(acc) : "l"(a), "l"(b))

// ---------------- scratch (device globals; zero-initialized at load) -------
__device__ float g_buf_agg[NN * DIM];   // aggregated features / layer-3 g [N,64]
__device__ float g_buf_h[NN * DIM];     // hidden activations (pre-scaled by ns)
__device__ float g_norm_src[NN];
__device__ float g_norm_dst[NN];
__device__ float g_sns[NN];             // sum of norm_src over in-neighbors (reset tail)
__device__ int   g_deg_out[NN];         // reset tail
__device__ int   g_deg_in[NN];          // reset tail
__device__ int   g_off[NN];             // CSR offsets, exclusive WITHIN scan block
__device__ int   g_blockoff[NB];
__device__ int   g_blocksum[NB];
__device__ int   g_cursor[NN];          // reset tail
__device__ int   g_csr_src[NE];
__device__ float g_sum0[DIM], g_sumsq0[DIM];
__device__ float g_sum1[DIM], g_sumsq1[DIM];
__device__ float g_mean[DIM], g_rstd[DIM];

#define BUF_AGG 0
#define BUF_H   1
__device__ __forceinline__ const float* buf_sel(int s) {
    return (s == BUF_AGG) ? g_buf_agg : g_buf_h;
}
__device__ __forceinline__ float* buf_sel_w(int s) {
    return (s == BUF_AGG) ? g_buf_agg : g_buf_h;
}

__device__ __forceinline__ int csr_start(int node) {
    return g_off[node] + g_blockoff[node >> 10];
}

// ---------------- setup -------------------------------------------------------
__global__ void k_count(const int* __restrict__ src, const int* __restrict__ dst) {
    int e = blockIdx.x * blockDim.x + threadIdx.x;
    if (e < NE) {
        atomicAdd(&g_deg_out[src[e]], 1);
        atomicAdd(&g_deg_in[dst[e]], 1);
    }
}

// local scan of deg_in + norms + BN-stat zeroing, fused
__global__ void __launch_bounds__(SCAN_B) k_scan_norms() {
    __shared__ int s[SCAN_B];
    int i = blockIdx.x * SCAN_B + threadIdx.x;
    int din = (i < NN) ? g_deg_in[i] : 0;
    s[threadIdx.x] = din;
    __syncthreads();
    #pragma unroll
    for (int off = 1; off < SCAN_B; off <<= 1) {
        int v = (threadIdx.x >= off) ? s[threadIdx.x - off] : 0;
        __syncthreads();
        s[threadIdx.x] += v;
        __syncthreads();
    }
    if (i < NN) {
        g_off[i] = s[threadIdx.x] - din;   // exclusive within block
        g_norm_src[i] = rsqrtf(fmaxf((float)g_deg_out[i], 1.0f));
        g_norm_dst[i] = rsqrtf(fmaxf((float)din, 1.0f));
    }
    if (threadIdx.x == SCAN_B - 1) g_blocksum[blockIdx.x] = s[SCAN_B - 1];
    if (blockIdx.x == 0 && threadIdx.x < DIM) {
        g_sum0[threadIdx.x] = 0.f; g_sumsq0[threadIdx.x] = 0.f;
        g_sum1[threadIdx.x] = 0.f; g_sumsq1[threadIdx.x] = 0.f;
    }
}

__global__ void k_scan_block() {
    __shared__ int s[NB];
    if (threadIdx.x < NB) s[threadIdx.x] = g_blocksum[threadIdx.x];
    __syncthreads();
    if (threadIdx.x == 0) {
        int acc = 0;
        for (int b = 0; b < NB; ++b) { int v = s[b]; s[b] = acc; acc += v; }
    }
    __syncthreads();
    if (threadIdx.x < NB) g_blockoff[threadIdx.x] = s[threadIdx.x];
}

// CSR fill + accumulate sns[d]
__global__ void k_fill_csr(const int* __restrict__ src, const int* __restrict__ dst) {
    int e = blockIdx.x * blockDim.x + threadIdx.x;
    if (e < NE) {
        int d = dst[e];
        int s = src[e];
        int pos = atomicAdd(&g_cursor[d], 1);
        g_csr_src[g_off[d] + g_blockoff[d >> 10] + pos] = s;
        atomicAdd(&g_sns[d], g_norm_src[s]);
    }
}

// ---------------- pull, layer 1 (raw features, per-edge norm) -----------------
__global__ void __launch_bounds__(256) k_pull128_l1(const float* __restrict__ h) {
    int t = blockIdx.x * blockDim.x + threadIdx.x;
    int node = t >> 5;
    if (node >= NN) return;
    int lane = t & 31;
    int c = lane << 2;
    int start = csr_start(node);
    int n = g_deg_in[node];

    float4 a0 = make_float4(0.f, 0.f, 0.f, 0.f);
    float4 a1 = make_float4(0.f, 0.f, 0.f, 0.f);

    int j = 0;
    int end4 = n & ~3;
    for (; j < end4; j += 4) {
        int s0 = __ldg(&g_csr_src[start + j]);
        int s1 = __ldg(&g_csr_src[start + j + 1]);
        int s2 = __ldg(&g_csr_src[start + j + 2]);
        int s3 = __ldg(&g_csr_src[start + j + 3]);
        float n0 = __ldg(&g_norm_src[s0]);
        float n1 = __ldg(&g_norm_src[s1]);
        float n2 = __ldg(&g_norm_src[s2]);
        float n3 = __ldg(&g_norm_src[s3]);
        float4 v0 = *reinterpret_cast<const float4*>(h + (size_t)s0 * DIM + c);
        float4 v1 = *reinterpret_cast<const float4*>(h + (size_t)s1 * DIM + c);
        float4 v2 = *reinterpret_cast<const float4*>(h + (size_t)s2 * DIM + c);
        float4 v3 = *reinterpret_cast<const float4*>(h + (size_t)s3 * DIM + c);
        a0.x = fmaf(n0, v0.x, a0.x); a0.y = fmaf(n0, v0.y, a0.y);
        a0.z = fmaf(n0, v0.z, a0.z); a0.w = fmaf(n0, v0.w, a0.w);
        a1.x = fmaf(n1, v1.x, a1.x); a1.y = fmaf(n1, v1.y, a1.y);
        a1.z = fmaf(n1, v1.z, a1.z); a1.w = fmaf(n1, v1.w, a1.w);
        a0.x = fmaf(n2, v2.x, a0.x); a0.y = fmaf(n2, v2.y, a0.y);
        a0.z = fmaf(n2, v2.z, a0.z); a0.w = fmaf(n2, v2.w, a0.w);
        a1.x = fmaf(n3, v3.x, a1.x); a1.y = fmaf(n3, v3.y, a1.y);
        a1.z = fmaf(n3, v3.z, a1.z); a1.w = fmaf(n3, v3.w, a1.w);
    }
    for (; j < n; ++j) {
        int s0 = __ldg(&g_csr_src[start + j]);
        float n0 = __ldg(&g_norm_src[s0]);
        float4 v0 = *reinterpret_cast<const float4*>(h + (size_t)s0 * DIM + c);
        a0.x = fmaf(n0, v0.x, a0.x); a0.y = fmaf(n0, v0.y, a0.y);
        a0.z = fmaf(n0, v0.z, a0.z); a0.w = fmaf(n0, v0.w, a0.w);
    }
    a0.x += a1.x; a0.y += a1.y; a0.z += a1.z; a0.w += a1.w;

    float nd = g_norm_dst[node];
    a0.x *= nd; a0.y *= nd; a0.z *= nd; a0.w *= nd;
    *reinterpret_cast<float4*>(g_buf_agg + (size_t)node * DIM + c) = a0;
}

// ---------------- pull, layer 2 (pure row-sum; h pre-scaled by ns) -----------
__global__ void __launch_bounds__(256) k_pull128_fast() {
    int t = blockIdx.x * blockDim.x + threadIdx.x;
    int node = t >> 5;
    if (node >= NN) return;
    const float* __restrict__ h = g_buf_h;
    int lane = t & 31;
    int c = lane << 2;
    int start = csr_start(node);
    int n = g_deg_in[node];

    float4 a0 = make_float4(0.f, 0.f, 0.f, 0.f);
    float4 a1 = make_float4(0.f, 0.f, 0.f, 0.f);

    int j = 0;
    int end4 = n & ~3;
    for (; j < end4; j += 4) {
        int s0 = __ldg(&g_csr_src[start + j]);
        int s1 = __ldg(&g_csr_src[start + j + 1]);
        int s2 = __ldg(&g_csr_src[start + j + 2]);
        int s3 = __ldg(&g_csr_src[start + j + 3]);
        float4 v0 = *reinterpret_cast<const float4*>(h + (size_t)s0 * DIM + c);
        float4 v1 = *reinterpret_cast<const float4*>(h + (size_t)s1 * DIM + c);
        float4 v2 = *reinterpret_cast<const float4*>(h + (size_t)s2 * DIM + c);
        float4 v3 = *reinterpret_cast<const float4*>(h + (size_t)s3 * DIM + c);
        a0.x += v0.x + v2.x; a0.y += v0.y + v2.y;
        a0.z += v0.z + v2.z; a0.w += v0.w + v2.w;
        a1.x += v1.x + v3.x; a1.y += v1.y + v3.y;
        a1.z += v1.z + v3.z; a1.w += v1.w + v3.w;
    }
    for (; j < n; ++j) {
        int s0 = __ldg(&g_csr_src[start + j]);
        float4 v0 = *reinterpret_cast<const float4*>(h + (size_t)s0 * DIM + c);
        a0.x += v0.x; a0.y += v0.y; a0.z += v0.z; a0.w += v0.w;
    }
    a0.x += a1.x; a0.y += a1.y; a0.z += a1.z; a0.w += a1.w;

    float sns = g_sns[node];
    float nd  = g_norm_dst[node];
    float4 m  = *reinterpret_cast<const float4*>(g_mean + c);
    float4 rs = *reinterpret_cast<const float4*>(g_rstd + c);
    a0.x = (a0.x - m.x * sns) * rs.x * nd;
    a0.y = (a0.y - m.y * sns) * rs.y * nd;
    a0.z = (a0.z - m.z * sns) * rs.z * nd;
    a0.w = (a0.w - m.w * sns) * rs.w * nd;
    *reinterpret_cast<float4*>(g_buf_agg + (size_t)node * DIM + c) = a0;
}

// ---------------- pull, final layer (64 wide) ---------------------------------
__global__ void __launch_bounds__(256) k_pull64(float* __restrict__ out,
                                                const float* __restrict__ b2) {
    int t = blockIdx.x * blockDim.x + threadIdx.x;
    int node = t >> 4;
    if (node >= NN) return;
    const float* __restrict__ g = g_buf_agg;
    int lane = t & 15;
    int c = lane << 2;
    int start = csr_start(node);
    int n = g_deg_in[node];

    float4 a0 = make_float4(0.f, 0.f, 0.f, 0.f);
    float4 a1 = make_float4(0.f, 0.f, 0.f, 0.f);

    int j = 0;
    int end4 = n & ~3;
    for (; j < end4; j += 4) {
        int s0 = __ldg(&g_csr_src[start + j]);
        int s1 = __ldg(&g_csr_src[start + j + 1]);
        int s2 = __ldg(&g_csr_src[start + j + 2]);
        int s3 = __ldg(&g_csr_src[start + j + 3]);
        float4 v0 = *reinterpret_cast<const float4*>(g + (size_t)s0 * DC + c);
        float4 v1 = *reinterpret_cast<const float4*>(g + (size_t)s1 * DC + c);
        float4 v2 = *reinterpret_cast<const float4*>(g + (size_t)s2 * DC + c);
        float4 v3 = *reinterpret_cast<const float4*>(g + (size_t)s3 * DC + c);
        a0.x += v0.x + v2.x; a0.y += v0.y + v2.y;
        a0.z += v0.z + v2.z; a0.w += v0.w + v2.w;
        a1.x += v1.x + v3.x; a1.y += v1.y + v3.y;
        a1.z += v1.z + v3.z; a1.w += v1.w + v3.w;
    }
    for (; j < n; ++j) {
        int s0 = __ldg(&g_csr_src[start + j]);
        float4 v0 = *reinterpret_cast<const float4*>(g + (size_t)s0 * DC + c);
        a0.x += v0.x; a0.y += v0.y; a0.z += v0.z; a0.w += v0.w;
    }
    a0.x += a1.x; a0.y += a1.y; a0.z += a1.z; a0.w += a1.w;

    float nd = g_norm_dst[node];
    float4 b = *reinterpret_cast<const float4*>(b2 + c);
    a0.x = fmaf(a0.x, nd, b.x);
    a0.y = fmaf(a0.y, nd, b.y);
    a0.z = fmaf(a0.z, nd, b.z);
    a0.w = fmaf(a0.w, nd, b.w);
    *reinterpret_cast<float4*>(out + (size_t)node * DC + c) = a0;
}

// ---------------- fused GEMM (f32x2 packed inner loop) -------------------------
// XFORM: 0 none; 1 = (v - mean*ns[row]) * rstd   (layer-3 input, h pre-scaled)
// OUT_SCALE: multiply stored output by ns[row] (stats computed pre-scale)
// STATS: -1 none, 0 -> sum0, 1 -> sum1
template<int OUTW, int IN_SEL, int OUT_SEL, int XFORM, bool BIAS_RELU, bool OUT_SCALE, int STATS>
__global__ void __launch_bounds__(256) k_gemm(const float* __restrict__ W,
                                              const float* __restrict__ bias) {
    constexpr int CT = OUTW / 16;       // cols per thread (8 or 4)
    constexpr int CP = CT / 2;          // packed col-pairs per thread (4 or 2)
    __shared__ float As[64 * 132];

    const float* __restrict__ A = buf_sel(IN_SEL);
    float* __restrict__ out = buf_sel_w(OUT_SEL);

    int rowBase = blockIdx.x * 64;

    #pragma unroll
    for (int it = 0; it < 8; ++it) {
        int idx = threadIdx.x + it * 256;
        int r   = idx >> 5;
        int c   = (idx & 31) << 2;
        int row = rowBase + r;
        float4 v = make_float4(0.f, 0.f, 0.f, 0.f);
        if (row < NN) {
            v = *reinterpret_cast<const float4*>(A + (size_t)row * DIM + c);
            if (XFORM == 1) {
                float ns = g_norm_src[row];
                float4 m  = *reinterpret_cast<const float4*>(g_mean + c);
                float4 rs = *reinterpret_cast<const float4*>(g_rstd + c);
                v.x = (v.x - m.x * ns) * rs.x;
                v.y = (v.y - m.y * ns) * rs.y;
                v.z = (v.z - m.z * ns) * rs.z;
                v.w = (v.w - m.w * ns) * rs.w;
            }
        }
        *reinterpret_cast<float4*>(&As[r * 132 + c]) = v;
    }
    __syncthreads();

    int tr = threadIdx.x >> 4;
    int tc = threadIdx.x & 15;
    const float* A0 = &As[(tr * 4) * 132];

    u64 acc[4][CP];
    #pragma unroll
    for (int i = 0; i < 4; ++i)
        #pragma unroll
        for (int j = 0; j < CP; ++j) acc[i][j] = 0ull;

    const float* wbase = W + tc * CT;

    #pragma unroll 4
    for (int k = 0; k < 128; ++k) {
        u64 a0 = pack_dup(A0[k]);
        u64 a1 = pack_dup(A0[132 + k]);
        u64 a2 = pack_dup(A0[264 + k]);
        u64 a3 = pack_dup(A0[396 + k]);
        u64 w[CP];
        {
            const float* wrow = wbase + k * OUTW;
            asm("ld.global.nc.v2.u64 {%0, %1}, [%2];"
                : "=l"(w[0]), "=l"(w[1]) : "l"(wrow));
            if (CP == 4) {
                asm("ld.global.nc.v2.u64 {%0, %1}, [%2];"
                    : "=l"(w[2]), "=l"(w[3]) : "l"(wrow + 4));
            }
        }
        #pragma unroll
        for (int j = 0; j < CP; ++j) {
            FMA2(acc[0][j], a0, w[j]);
            FMA2(acc[1][j], a1, w[j]);
            FMA2(acc[2][j], a2, w[j]);
            FMA2(acc[3][j], a3, w[j]);
        }
    }

    // epilogue: unpack, bias+relu, store; keep values for stats
    float res[4][CT];
    float bv[CT];
    if (BIAS_RELU) {
        #pragma unroll
        for (int j0 = 0; j0 < CT; j0 += 4) {
            float4 b = __ldg(reinterpret_cast<const float4*>(bias + tc * CT + j0));
            bv[j0] = b.x; bv[j0 + 1] = b.y; bv[j0 + 2] = b.z; bv[j0 + 3] = b.w;
        }
    }
    #pragma unroll
    for (int i = 0; i < 4; ++i) {
        int row = rowBase + tr * 4 + i;
        bool valid = row < NN;
        #pragma unroll
        for (int j = 0; j < CP; ++j) {
            float lo, hi;
            unpack2(acc[i][j], lo, hi);
            if (BIAS_RELU) {
                lo = fmaxf(lo + bv[2 * j], 0.f);
                hi = fmaxf(hi + bv[2 * j + 1], 0.f);
            }
            res[i][2 * j]     = valid ? lo : 0.f;
            res[i][2 * j + 1] = valid ? hi : 0.f;
        }
        if (valid) {
            float osc = OUT_SCALE ? __ldg(&g_norm_src[row]) : 1.0f;
            #pragma unroll
            for (int j0 = 0; j0 < CT; j0 += 4) {
                float4 y4;
                y4.x = res[i][j0 + 0] * osc; y4.y = res[i][j0 + 1] * osc;
                y4.z = res[i][j0 + 2] * osc; y4.w = res[i][j0 + 3] * osc;
                *reinterpret_cast<float4*>(out + (size_t)row * OUTW + tc * CT + j0) = y4;
            }
        }
    }

    if (STATS >= 0) {
        float* SUM = (STATS == 0) ? g_sum0 : g_sum1;
        float* SQ  = (STATS == 0) ? g_sumsq0 : g_sumsq1;
        float* sh = As;
        __syncthreads();
        #pragma unroll
        for (int j = 0; j < CT; ++j) {
            float s = (res[0][j] + res[1][j]) + (res[2][j] + res[3][j]);
            float q = fmaf(res[0][j], res[0][j],
                      fmaf(res[1][j], res[1][j],
                      fmaf(res[2][j], res[2][j], res[3][j] * res[3][j])));
            int col = tc * CT + j;
            sh[tr * 128 + col] = s;
            sh[2048 + tr * 128 + col] = q;
        }
        __syncthreads();
        if (threadIdx.x < 128) {
            int col = threadIdx.x;
            float s = 0.f, q = 0.f;
            #pragma unroll
            for (int k2 = 0; k2 < 16; ++k2) {
                s += sh[k2 * 128 + col];
                q += sh[2048 + k2 * 128 + col];
            }
            atomicAdd(&SUM[col], s);
            atomicAdd(&SQ[col], q);
        }
    }
}

// ---------------- finalize BN stats -------------------------------------------
template<int L>
__global__ void k_finalize_stats() {
    int i = threadIdx.x;
    if (i < DIM) {
        const float* S = (L == 0) ? g_sum0 : g_sum1;
        const float* Q = (L == 0) ? g_sumsq0 : g_sumsq1;
        float inv = 1.0f / (float)NN;
        float mean = S[i] * inv;
        float var  = fmaxf(Q[i] * inv - mean * mean, 0.f);
        g_mean[i] = mean;
        g_rstd[i] = rsqrtf(var + BN_EPS);
    }
}

// ---------------- tail reset ----------------------------------------------------
__global__ void k_reset() {
    int i = blockIdx.x * blockDim.x + threadIdx.x;
    if (i < NN) {
        g_deg_out[i] = 0; g_deg_in[i] = 0;
        g_cursor[i] = 0;  g_sns[i] = 0.f;
    }
}

// ---------------- launch ---------------------------------------------------------
extern "C" void kernel_launch(void* const* d_in, const int* in_sizes, int n_in,
                              void* d_out, int out_size) {
    const float* features = (const float*)d_in[0];
    const float* W0 = (const float*)d_in[1];
    const float* b0 = (const float*)d_in[2];
    const float* W1 = (const float*)d_in[3];
    const float* b1 = (const float*)d_in[4];
    const float* W2 = (const float*)d_in[5];
    const float* b2 = (const float*)d_in[6];
    const int* src = (const int*)d_in[7];
    const int* dst = (const int*)d_in[8];
    float* out = (float*)d_out;

    const int TB = 256;
    const int gN      = (NN + TB - 1) / TB;
    const int gE      = (NE + TB - 1) / TB;
    const int gPull   = (NN * 32 + TB - 1) / TB;
    const int gPull64 = (NN * 16 + TB - 1) / TB;
    const int gGemm   = (NN + 63) / 64;

    // setup (counters arrive zeroed: zero-init first call, k_reset tail after)
    k_count<<<gE, TB>>>(src, dst);          // #1
    k_scan_norms<<<NB, SCAN_B>>>();         // #2 (scan + norms + stat-zero)
    k_scan_block<<<1, 128>>>();             // #3
    k_fill_csr<<<gE, TB>>>(src, dst);       // #4 (profiled slot)

    // layer 1: agg = nd * A~(ns*feat); h' = ns * relu(agg @ W0 + b0); stats on h
    k_pull128_l1<<<gPull, TB>>>(features);
    k_gemm<128, BUF_AGG, BUF_H, 0, true, true, 0><<<gGemm, TB>>>(W0, b0);
    k_finalize_stats<0><<<1, 128>>>();

    // layer 2: pure-sum pull with BN-fold epilogue; h' = ns * relu(...)
    k_pull128_fast<<<gPull, TB>>>();
    k_gemm<128, BUF_AGG, BUF_H, 0, true, true, 1><<<gGemm, TB>>>(W1, b1);
    k_finalize_stats<1><<<1, 128>>>();

    // layer 3: g = ((h' - m*ns)*rs) @ W2, then pure-sum pull + nd,b2 epilogue
    k_gemm<64, BUF_H, BUF_AGG, 1, false, false, -1><<<gGemm, TB>>>(W2, nullptr);
    k_pull64<<<gPull64, TB>>>(out, b2);

    // leave counters zeroed for next invocation
    k_reset<<<gN, TB>>>();
}